// round 1
// baseline (speedup 1.0000x reference)
#include <cuda_runtime.h>
#include <cstdint>
#include <math.h>

#define KB 128      // batch k
#define NN 2048     // nodes
#define DD 512      // dim

// Scratch (no allocations allowed -> device globals)
__device__ float g_q[KB * DD];
__device__ float g_r[KB * DD];
__device__ float g_compat[KB * NN];

// ---------------------------------------------------------------------------
// Small tiled FP32 GEMM.
// MODE 0: g_q[k,e]   = sum_d  ctx[k,d] * Wq[e,d]     (A @ B^T)
// MODE 1: g_r[k,d]   = sum_e  g_q[k,e] * Wk[e,d]     (A @ B)
// M=128, N=512, K=512. Tiles BM=32, BN=64, BK=32. 256 threads, 2x4 microtile.
// ---------------------------------------------------------------------------
#define BM 32
#define BN 64
#define BKT 32

template<int MODE>
__global__ void gemm_kernel(const float* __restrict__ Ain,
                            const float* __restrict__ B) {
    const float* A = (MODE == 0) ? Ain : g_q;
    float* out     = (MODE == 0) ? g_q : g_r;
    const int Kd = DD;           // reduction length
    const int Nw = DD;           // output row width

    __shared__ float As[BKT][BM + 2];   // [kk][m], stride 34 (even -> float2 ok)
    __shared__ float Bs[BKT][BN + 4];   // [kk][n], stride 68 (mult of 4 -> float4 ok)

    int tid = threadIdx.x;
    int tx = tid & 15;    // n-group (4 cols each)
    int ty = tid >> 4;    // m-group (2 rows each)
    int m0 = blockIdx.y * BM;
    int n0 = blockIdx.x * BN;

    float acc[2][4] = {{0.f,0.f,0.f,0.f},{0.f,0.f,0.f,0.f}};

    for (int k0 = 0; k0 < Kd; k0 += BKT) {
        // ---- fill As (transposed): As[kk][m] = A[m0+m][k0+kk] ----
        {
            int m  = tid >> 3;
            int c4 = (tid & 7) * 4;
            float4 v = *(const float4*)&A[(size_t)(m0 + m) * Kd + k0 + c4];
            As[c4 + 0][m] = v.x; As[c4 + 1][m] = v.y;
            As[c4 + 2][m] = v.z; As[c4 + 3][m] = v.w;
        }
        // ---- fill Bs: Bs[kk][n] ----
        if (MODE == 0) {
            // B^T access: Bs[kk][n] = B[n0+n][k0+kk]
            #pragma unroll
            for (int r = 0; r < 2; r++) {
                int idx = tid + r * 256;
                int n  = idx >> 3;
                int c4 = (idx & 7) * 4;
                float4 v = *(const float4*)&B[(size_t)(n0 + n) * Kd + k0 + c4];
                Bs[c4 + 0][n] = v.x; Bs[c4 + 1][n] = v.y;
                Bs[c4 + 2][n] = v.z; Bs[c4 + 3][n] = v.w;
            }
        } else {
            // direct: Bs[kk][n] = B[k0+kk][n0+n]
            #pragma unroll
            for (int r = 0; r < 2; r++) {
                int idx = tid + r * 256;
                int kk = idx >> 4;           // 16 float4 per row of 64
                int c4 = (idx & 15) * 4;
                float4 v = *(const float4*)&B[(size_t)(k0 + kk) * Nw + n0 + c4];
                *(float4*)&Bs[kk][c4] = v;
            }
        }
        __syncthreads();

        #pragma unroll
        for (int kk = 0; kk < BKT; kk++) {
            float2 a = *(const float2*)&As[kk][ty * 2];
            float4 b = *(const float4*)&Bs[kk][tx * 4];
            acc[0][0] += a.x * b.x; acc[0][1] += a.x * b.y;
            acc[0][2] += a.x * b.z; acc[0][3] += a.x * b.w;
            acc[1][0] += a.y * b.x; acc[1][1] += a.y * b.y;
            acc[1][2] += a.y * b.z; acc[1][3] += a.y * b.w;
        }
        __syncthreads();
    }

    #pragma unroll
    for (int i = 0; i < 2; i++) {
        float4 st = make_float4(acc[i][0], acc[i][1], acc[i][2], acc[i][3]);
        *(float4*)&out[(size_t)(m0 + ty * 2 + i) * Nw + n0 + tx * 4] = st;
    }
}

// ---------------------------------------------------------------------------
// Streaming dot: compat[k,n] = tanh(clip(r[k]·node[k,n], -10, 10)) / sqrt(512)
// One warp per node, 16 nodes per warp. grid (16, 128), 256 threads.
// Each lane: 4x LDG.128 per node against 16 register-resident r values.
// ---------------------------------------------------------------------------
__global__ void dot_kernel(const float* __restrict__ nodes) {
    int k    = blockIdx.y;
    int warp = threadIdx.x >> 5;
    int lane = threadIdx.x & 31;

    const float4* r4 = (const float4*)(g_r + (size_t)k * DD);
    float4 r0 = r4[lane];
    float4 r1 = r4[lane + 32];
    float4 r2 = r4[lane + 64];
    float4 r3 = r4[lane + 96];

    const float4* base = (const float4*)(nodes + (size_t)k * NN * DD);
    int node0 = blockIdx.x * 128 + warp * 16;

    const float inv_sqrt_d = 0.04419417382415922f;  // 1/sqrt(512)

    #pragma unroll 2
    for (int i = 0; i < 16; i++) {
        const float4* p = base + (size_t)(node0 + i) * (DD / 4);
        float4 a = p[lane];
        float4 b = p[lane + 32];
        float4 c = p[lane + 64];
        float4 d = p[lane + 96];
        float s = a.x * r0.x + a.y * r0.y + a.z * r0.z + a.w * r0.w
                + b.x * r1.x + b.y * r1.y + b.z * r1.z + b.w * r1.w
                + c.x * r2.x + c.y * r2.y + c.z * r2.z + c.w * r2.w
                + d.x * r3.x + d.y * r3.y + d.z * r3.z + d.w * r3.w;
        #pragma unroll
        for (int o = 16; o > 0; o >>= 1)
            s += __shfl_xor_sync(0xFFFFFFFFu, s, o);
        if (lane == 0) {
            float t = tanhf(fminf(fmaxf(s, -10.f), 10.f)) * inv_sqrt_d;
            g_compat[(size_t)k * NN + node0 + i] = t;
        }
    }
}

// ---------------------------------------------------------------------------
// Masked softmax over N=2048 per row. One block per k. 256 threads x 8 elems.
// Mask dtype sniffed from the first 16 words (int32 0/1, float 0.0/1.0, else u8).
// ---------------------------------------------------------------------------
__global__ void softmax_kernel(const unsigned char* __restrict__ mask,
                               float* __restrict__ out) {
    int k   = blockIdx.x;
    int tid = threadIdx.x;

    // dtype sniff (same result in every thread; deterministic)
    const unsigned* mw = (const unsigned*)mask;
    bool i32 = true, f32 = true;
    #pragma unroll
    for (int i = 0; i < 16; i++) {
        unsigned w = mw[i];
        i32 = i32 && (w <= 1u);
        f32 = f32 && (w == 0u || w == 0x3F800000u);
    }

    const float* cmp = g_compat + (size_t)k * NN;
    float v[8];
    float mx = -1e30f;
    #pragma unroll
    for (int j = 0; j < 8; j++) {
        int idx = tid + j * 256;
        size_t gi = (size_t)k * NN + idx;
        bool m;
        if (i32)      m = ((const int*)mask)[gi] != 0;
        else if (f32) m = ((const float*)mask)[gi] != 0.f;
        else          m = mask[gi] != 0;
        float c = cmp[idx];
        v[j] = m ? -INFINITY : c;
        mx = fmaxf(mx, v[j]);
    }

    __shared__ float red[8];
    #pragma unroll
    for (int o = 16; o > 0; o >>= 1)
        mx = fmaxf(mx, __shfl_xor_sync(0xFFFFFFFFu, mx, o));
    if ((tid & 31) == 0) red[tid >> 5] = mx;
    __syncthreads();
    float bm = red[0];
    #pragma unroll
    for (int i = 1; i < 8; i++) bm = fmaxf(bm, red[i]);
    __syncthreads();

    float s = 0.f;
    #pragma unroll
    for (int j = 0; j < 8; j++) {
        v[j] = __expf(v[j] - bm);    // exp(-inf) = 0 for masked entries
        s += v[j];
    }
    #pragma unroll
    for (int o = 16; o > 0; o >>= 1)
        s += __shfl_xor_sync(0xFFFFFFFFu, s, o);
    if ((tid & 31) == 0) red[tid >> 5] = s;
    __syncthreads();
    float tot = 0.f;
    #pragma unroll
    for (int i = 0; i < 8; i++) tot += red[i];
    float inv = 1.f / tot;

    #pragma unroll
    for (int j = 0; j < 8; j++)
        out[(size_t)k * NN + tid + j * 256] = v[j] * inv;
}

// ---------------------------------------------------------------------------
extern "C" void kernel_launch(void* const* d_in, const int* in_sizes, int n_in,
                              void* d_out, int out_size) {
    const float* ctx   = (const float*)d_in[0];  // [128, 512]
    const float* nodes = (const float*)d_in[1];  // [128, 2048, 512]
    const unsigned char* mask = (const unsigned char*)d_in[2];  // [128, 2048] bool
    const float* Wq    = (const float*)d_in[3];  // [512, 512]
    const float* Wk    = (const float*)d_in[4];  // [512, 512]
    // d_in[5] = Wv: dead code in the reference output, skipped.
    float* out = (float*)d_out;                  // [128, 2048]

    gemm_kernel<0><<<dim3(DD / BN, KB / BM), 256>>>(ctx, Wq);      // q = c @ Wq^T
    gemm_kernel<1><<<dim3(DD / BN, KB / BM), 256>>>(nullptr, Wk);  // r = q @ Wk
    dot_kernel<<<dim3(NN / 128, KB), 256>>>(nodes);                // compat
    softmax_kernel<<<KB, 256>>>(mask, out);                        // masked softmax
}

// round 2
// speedup vs baseline: 1.3415x; 1.3415x over previous
#include <cuda_runtime.h>
#include <cstdint>
#include <math.h>

#define KB 128      // batch k
#define NN 2048     // nodes
#define DD 512      // dim

// Scratch (no allocations allowed -> device globals)
__device__ float g_q[KB * DD];
__device__ float g_r[KB * DD];
__device__ float g_compat[KB * NN];

// ---------------------------------------------------------------------------
// Small tiled FP32 GEMM, occupancy-first: grid (16,8)=128 CTAs (1 per SM).
// MODE 0: g_q[k,e] = sum_d ctx[k,d] * Wq[e,d]   (A @ B^T)
// MODE 1: g_r[k,d] = sum_e g_q[k,e] * Wk[e,d]   (A @ B)
// M=128, N=512, K=512. BM=16, BN=32, BK=64. 256 threads, 1x2 microtile.
// Register prefetch of next K-slab overlaps global latency with compute.
// ---------------------------------------------------------------------------
#define BM 16
#define BN 32
#define BKT 64
#define BS_STRIDE 36   // multiple of 4 -> float4 STS ok, shifts banks per kk

template<int MODE>
__global__ void gemm_kernel(const float* __restrict__ Ain,
                            const float* __restrict__ B) {
    const float* A = (MODE == 0) ? Ain : g_q;
    float* out     = (MODE == 0) ? g_q : g_r;

    __shared__ float As[BKT][BM + 1];        // [kk][m]
    __shared__ float Bs[BKT][BS_STRIDE];     // [kk][n]

    int tid = threadIdx.x;
    int tx = tid & 15;    // n-group (2 cols)
    int ty = tid >> 4;    // m row (16 rows)
    int m0 = blockIdx.y * BM;
    int n0 = blockIdx.x * BN;

    // ---- global-load index precompute ----
    // A: m = tid>>4, c4 = (tid&15)*4  -> covers 16m x 64k
    int am  = tid >> 4;
    int ac4 = (tid & 15) * 4;
    // B mode0: idx=tid+r*256; n=idx>>4, c4=(idx&15)*4  (vector along k)
    // B mode1: idx=tid+r*256; kk=idx>>3, c4=(idx&7)*4  (vector along n)

    float4 pa, pb[2];

    // prefetch k0 = 0
    {
        pa = *(const float4*)&A[(size_t)(m0 + am) * DD + ac4];
        #pragma unroll
        for (int r = 0; r < 2; r++) {
            int idx = tid + r * 256;
            if (MODE == 0) {
                int n = idx >> 4, c4 = (idx & 15) * 4;
                pb[r] = *(const float4*)&B[(size_t)(n0 + n) * DD + c4];
            } else {
                int kk = idx >> 3, c4 = (idx & 7) * 4;
                pb[r] = *(const float4*)&B[(size_t)kk * DD + n0 + c4];
            }
        }
    }

    float acc0 = 0.f, acc1 = 0.f;

    for (int it = 0; it < DD / BKT; it++) {
        // ---- commit prefetched slab to smem ----
        As[ac4 + 0][am] = pa.x; As[ac4 + 1][am] = pa.y;
        As[ac4 + 2][am] = pa.z; As[ac4 + 3][am] = pa.w;
        #pragma unroll
        for (int r = 0; r < 2; r++) {
            int idx = tid + r * 256;
            if (MODE == 0) {
                int n = idx >> 4, c4 = (idx & 15) * 4;
                Bs[c4 + 0][n] = pb[r].x; Bs[c4 + 1][n] = pb[r].y;
                Bs[c4 + 2][n] = pb[r].z; Bs[c4 + 3][n] = pb[r].w;
            } else {
                int kk = idx >> 3, c4 = (idx & 7) * 4;
                *(float4*)&Bs[kk][c4] = pb[r];
            }
        }
        __syncthreads();

        // ---- prefetch next slab into registers ----
        if (it + 1 < DD / BKT) {
            int k0 = (it + 1) * BKT;
            pa = *(const float4*)&A[(size_t)(m0 + am) * DD + k0 + ac4];
            #pragma unroll
            for (int r = 0; r < 2; r++) {
                int idx = tid + r * 256;
                if (MODE == 0) {
                    int n = idx >> 4, c4 = (idx & 15) * 4;
                    pb[r] = *(const float4*)&B[(size_t)(n0 + n) * DD + k0 + c4];
                } else {
                    int kk = idx >> 3, c4 = (idx & 7) * 4;
                    pb[r] = *(const float4*)&B[(size_t)(k0 + kk) * DD + n0 + c4];
                }
            }
        }

        // ---- compute ----
        #pragma unroll
        for (int kk = 0; kk < BKT; kk++) {
            float a = As[kk][ty];
            float2 b = *(const float2*)&Bs[kk][tx * 2];
            acc0 += a * b.x;
            acc1 += a * b.y;
        }
        __syncthreads();
    }

    *(float2*)&out[(size_t)(m0 + ty) * DD + n0 + tx * 2] = make_float2(acc0, acc1);
}

// ---------------------------------------------------------------------------
// Streaming dot: compat[k,n] = tanh(clip(r[k]·node[k,n], -10, 10)) / sqrt(512)
// grid (32, 128), 256 threads. One warp handles 8 nodes, 2 concurrently:
// 8 independent LDG.128 (.cs streaming) in flight per pair, two interleaved
// shuffle-reduction chains, paired float2 store.
// ---------------------------------------------------------------------------
__global__ void dot_kernel(const float* __restrict__ nodes) {
    int k    = blockIdx.y;
    int warp = threadIdx.x >> 5;
    int lane = threadIdx.x & 31;

    const float4* r4 = (const float4*)(g_r + (size_t)k * DD);
    float4 r0 = __ldg(r4 + lane);
    float4 r1 = __ldg(r4 + lane + 32);
    float4 r2 = __ldg(r4 + lane + 64);
    float4 r3 = __ldg(r4 + lane + 96);

    const float4* base = (const float4*)(nodes + (size_t)k * NN * DD);
    int node0 = blockIdx.x * 64 + warp * 8;

    const float inv_sqrt_d = 0.04419417382415922f;  // 1/sqrt(512)

    #pragma unroll
    for (int i = 0; i < 8; i += 2) {
        const float4* p0 = base + (size_t)(node0 + i) * (DD / 4);
        const float4* p1 = p0 + (DD / 4);

        float4 a0 = __ldcs(p0 + lane);
        float4 b0 = __ldcs(p0 + lane + 32);
        float4 c0 = __ldcs(p0 + lane + 64);
        float4 d0 = __ldcs(p0 + lane + 96);
        float4 a1 = __ldcs(p1 + lane);
        float4 b1 = __ldcs(p1 + lane + 32);
        float4 c1 = __ldcs(p1 + lane + 64);
        float4 d1 = __ldcs(p1 + lane + 96);

        float s0 = a0.x * r0.x + a0.y * r0.y + a0.z * r0.z + a0.w * r0.w
                 + b0.x * r1.x + b0.y * r1.y + b0.z * r1.z + b0.w * r1.w
                 + c0.x * r2.x + c0.y * r2.y + c0.z * r2.z + c0.w * r2.w
                 + d0.x * r3.x + d0.y * r3.y + d0.z * r3.z + d0.w * r3.w;
        float s1 = a1.x * r0.x + a1.y * r0.y + a1.z * r0.z + a1.w * r0.w
                 + b1.x * r1.x + b1.y * r1.y + b1.z * r1.z + b1.w * r1.w
                 + c1.x * r2.x + c1.y * r2.y + c1.z * r2.z + c1.w * r2.w
                 + d1.x * r3.x + d1.y * r3.y + d1.z * r3.z + d1.w * r3.w;

        // two independent butterfly chains (ILP hides SHFL latency)
        #pragma unroll
        for (int o = 16; o > 0; o >>= 1) {
            s0 += __shfl_xor_sync(0xFFFFFFFFu, s0, o);
            s1 += __shfl_xor_sync(0xFFFFFFFFu, s1, o);
        }
        if (lane == 0) {
            float t0 = tanhf(fminf(fmaxf(s0, -10.f), 10.f)) * inv_sqrt_d;
            float t1 = tanhf(fminf(fmaxf(s1, -10.f), 10.f)) * inv_sqrt_d;
            *(float2*)&g_compat[(size_t)k * NN + node0 + i] = make_float2(t0, t1);
        }
    }
}

// ---------------------------------------------------------------------------
// Masked softmax over N=2048 per row. One block per k. 512 threads x 4 elems.
// Mask dtype sniffed from the first 16 words (int32 0/1, float 0.0/1.0, else u8).
// ---------------------------------------------------------------------------
__global__ void softmax_kernel(const unsigned char* __restrict__ mask,
                               float* __restrict__ out) {
    int k   = blockIdx.x;
    int tid = threadIdx.x;

    // dtype sniff (same result in every thread; deterministic)
    const unsigned* mw = (const unsigned*)mask;
    bool i32 = true, f32 = true;
    #pragma unroll
    for (int i = 0; i < 16; i++) {
        unsigned w = mw[i];
        i32 = i32 && (w <= 1u);
        f32 = f32 && (w == 0u || w == 0x3F800000u);
    }

    const float* cmp = g_compat + (size_t)k * NN;
    float v[4];
    float mx = -1e30f;
    #pragma unroll
    for (int j = 0; j < 4; j++) {
        int idx = tid + j * 512;
        size_t gi = (size_t)k * NN + idx;
        bool m;
        if (i32)      m = ((const int*)mask)[gi] != 0;
        else if (f32) m = ((const float*)mask)[gi] != 0.f;
        else          m = mask[gi] != 0;
        float c = cmp[idx];
        v[j] = m ? -INFINITY : c;
        mx = fmaxf(mx, v[j]);
    }

    __shared__ float red[16];
    #pragma unroll
    for (int o = 16; o > 0; o >>= 1)
        mx = fmaxf(mx, __shfl_xor_sync(0xFFFFFFFFu, mx, o));
    if ((tid & 31) == 0) red[tid >> 5] = mx;
    __syncthreads();
    float bm = red[0];
    #pragma unroll
    for (int i = 1; i < 16; i++) bm = fmaxf(bm, red[i]);
    __syncthreads();

    float s = 0.f;
    #pragma unroll
    for (int j = 0; j < 4; j++) {
        v[j] = __expf(v[j] - bm);    // exp(-inf) = 0 for masked entries
        s += v[j];
    }
    #pragma unroll
    for (int o = 16; o > 0; o >>= 1)
        s += __shfl_xor_sync(0xFFFFFFFFu, s, o);
    if ((tid & 31) == 0) red[tid >> 5] = s;
    __syncthreads();
    float tot = 0.f;
    #pragma unroll
    for (int i = 0; i < 16; i++) tot += red[i];
    float inv = 1.f / tot;

    #pragma unroll
    for (int j = 0; j < 4; j++)
        out[(size_t)k * NN + tid + j * 512] = v[j] * inv;
}

// ---------------------------------------------------------------------------
extern "C" void kernel_launch(void* const* d_in, const int* in_sizes, int n_in,
                              void* d_out, int out_size) {
    const float* ctx   = (const float*)d_in[0];  // [128, 512]
    const float* nodes = (const float*)d_in[1];  // [128, 2048, 512]
    const unsigned char* mask = (const unsigned char*)d_in[2];  // [128, 2048]
    const float* Wq    = (const float*)d_in[3];  // [512, 512]
    const float* Wk    = (const float*)d_in[4];  // [512, 512]
    // d_in[5] = Wv: dead code in the reference output, skipped.
    float* out = (float*)d_out;                  // [128, 2048]

    gemm_kernel<0><<<dim3(DD / BN, KB / BM), 256>>>(ctx, Wq);      // q = c @ Wq^T
    gemm_kernel<1><<<dim3(DD / BN, KB / BM), 256>>>(nullptr, Wk);  // r = q @ Wk
    dot_kernel<<<dim3(NN / 64, KB), 256>>>(nodes);                 // compat
    softmax_kernel<<<KB, 512>>>(mask, out);                        // masked softmax
}

// round 3
// speedup vs baseline: 1.7731x; 1.3217x over previous
#include <cuda_runtime.h>
#include <cstdint>
#include <math.h>

#define KB 128      // batch k
#define NN 2048     // nodes
#define DD 512      // dim

// Scratch (no allocations allowed -> device globals)
__device__ float g_q[KB * DD];
__device__ float g_r[KB * DD];
__device__ float g_exp[KB * NN];            // exp(compat) at original node index
__device__ float g_rowsum[KB];
__device__ unsigned short g_idx[KB * NN];   // compacted unmasked node indices
__device__ int g_cnt[KB];

// ---------------------------------------------------------------------------
// Mask dtype sniff: returns 0 = int32 (0/1), 1 = float32 (0.0/1.0), 2 = uint8.
// Deterministic; same result in every thread.
// ---------------------------------------------------------------------------
__device__ __forceinline__ int sniff_mask(const unsigned char* mask) {
    const unsigned* mw = (const unsigned*)mask;
    bool i32 = true, f32 = true;
    #pragma unroll
    for (int i = 0; i < 16; i++) {
        unsigned w = mw[i];
        i32 = i32 && (w <= 1u);
        f32 = f32 && (w == 0u || w == 0x3F800000u);
    }
    return i32 ? 0 : (f32 ? 1 : 2);
}

__device__ __forceinline__ bool mask_at(const unsigned char* mask, int mode, size_t gi) {
    if (mode == 0) return ((const int*)mask)[gi] != 0;
    if (mode == 1) return ((const float*)mask)[gi] != 0.f;
    return mask[gi] != 0;
}

// ---------------------------------------------------------------------------
// Small tiled FP32 GEMM, occupancy-first: grid (16,8)=128 CTAs.
// MODE 0: g_q[k,e] = sum_d ctx[k,d] * Wq[e,d]   (A @ B^T)
// MODE 1: g_r[k,d] = sum_e g_q[k,e] * Wk[e,d]   (A @ B)
// ---------------------------------------------------------------------------
#define BM 16
#define BN 32
#define BKT 64
#define BS_STRIDE 36

template<int MODE>
__global__ void gemm_kernel(const float* __restrict__ Ain,
                            const float* __restrict__ B) {
    const float* A = (MODE == 0) ? Ain : g_q;
    float* out     = (MODE == 0) ? g_q : g_r;

    __shared__ float As[BKT][BM + 1];
    __shared__ float Bs[BKT][BS_STRIDE];

    int tid = threadIdx.x;
    int tx = tid & 15;
    int ty = tid >> 4;
    int m0 = blockIdx.y * BM;
    int n0 = blockIdx.x * BN;

    int am  = tid >> 4;
    int ac4 = (tid & 15) * 4;

    float4 pa, pb[2];
    {
        pa = *(const float4*)&A[(size_t)(m0 + am) * DD + ac4];
        #pragma unroll
        for (int r = 0; r < 2; r++) {
            int idx = tid + r * 256;
            if (MODE == 0) {
                int n = idx >> 4, c4 = (idx & 15) * 4;
                pb[r] = *(const float4*)&B[(size_t)(n0 + n) * DD + c4];
            } else {
                int kk = idx >> 3, c4 = (idx & 7) * 4;
                pb[r] = *(const float4*)&B[(size_t)kk * DD + n0 + c4];
            }
        }
    }

    float acc0 = 0.f, acc1 = 0.f;

    for (int it = 0; it < DD / BKT; it++) {
        As[ac4 + 0][am] = pa.x; As[ac4 + 1][am] = pa.y;
        As[ac4 + 2][am] = pa.z; As[ac4 + 3][am] = pa.w;
        #pragma unroll
        for (int r = 0; r < 2; r++) {
            int idx = tid + r * 256;
            if (MODE == 0) {
                int n = idx >> 4, c4 = (idx & 15) * 4;
                Bs[c4 + 0][n] = pb[r].x; Bs[c4 + 1][n] = pb[r].y;
                Bs[c4 + 2][n] = pb[r].z; Bs[c4 + 3][n] = pb[r].w;
            } else {
                int kk = idx >> 3, c4 = (idx & 7) * 4;
                *(float4*)&Bs[kk][c4] = pb[r];
            }
        }
        __syncthreads();

        if (it + 1 < DD / BKT) {
            int k0 = (it + 1) * BKT;
            pa = *(const float4*)&A[(size_t)(m0 + am) * DD + k0 + ac4];
            #pragma unroll
            for (int r = 0; r < 2; r++) {
                int idx = tid + r * 256;
                if (MODE == 0) {
                    int n = idx >> 4, c4 = (idx & 15) * 4;
                    pb[r] = *(const float4*)&B[(size_t)(n0 + n) * DD + k0 + c4];
                } else {
                    int kk = idx >> 3, c4 = (idx & 7) * 4;
                    pb[r] = *(const float4*)&B[(size_t)(k0 + kk) * DD + n0 + c4];
                }
            }
        }

        #pragma unroll
        for (int kk = 0; kk < BKT; kk++) {
            float a = As[kk][ty];
            float2 b = *(const float2*)&Bs[kk][tx * 2];
            acc0 += a * b.x;
            acc1 += a * b.y;
        }
        __syncthreads();
    }

    *(float2*)&out[(size_t)(m0 + ty) * DD + n0 + tx * 2] = make_float2(acc0, acc1);
}

// ---------------------------------------------------------------------------
// Deterministic mask compaction: one CTA per row k (256 threads, 8 chunks).
// Writes compacted unmasked indices to g_idx[k], count to g_cnt[k].
// Also zeroes g_rowsum[k].
// ---------------------------------------------------------------------------
__global__ void compact_kernel(const unsigned char* __restrict__ mask) {
    int k   = blockIdx.x;
    int tid = threadIdx.x;
    int wid = tid >> 5;
    int lane = tid & 31;
    int mode = sniff_mask(mask);

    __shared__ int warp_sums[8];
    __shared__ int base_s;
    if (tid == 0) { base_s = 0; g_rowsum[k] = 0.f; }
    __syncthreads();

    for (int j = 0; j < 8; j++) {
        int n = j * 256 + tid;
        bool um = !mask_at(mask, mode, (size_t)k * NN + n);
        unsigned bal = __ballot_sync(0xFFFFFFFFu, um);
        int wpre = __popc(bal & ((1u << lane) - 1u));
        if (lane == 0) warp_sums[wid] = __popc(bal);
        __syncthreads();
        int wbase = 0;
        #pragma unroll
        for (int w = 0; w < 8; w++) if (w < wid) wbase += warp_sums[w];
        int pos = base_s + wbase + wpre;
        if (um) g_idx[(size_t)k * NN + pos] = (unsigned short)n;
        __syncthreads();
        if (tid == 0) {
            int tot = 0;
            #pragma unroll
            for (int w = 0; w < 8; w++) tot += warp_sums[w];
            base_s += tot;
        }
        __syncthreads();
    }
    if (tid == 0) g_cnt[k] = base_s;
}

// ---------------------------------------------------------------------------
// Streaming dot over COMPACTED (unmasked) nodes only:
//   e = exp( tanh(clip(r[k]·node, -10, 10)) / sqrt(512) )
// stored at original node position; per-CTA partial row sum via one atomicAdd.
// grid (32, 128), 256 threads; warp = 8 compacted slots, 2 concurrent.
// ---------------------------------------------------------------------------
__global__ void dot_kernel(const float* __restrict__ nodes) {
    int k    = blockIdx.y;
    int tid  = threadIdx.x;
    int warp = tid >> 5;
    int lane = tid & 31;
    int cnt  = g_cnt[k];

    const float4* r4 = (const float4*)(g_r + (size_t)k * DD);
    float4 r0 = __ldg(r4 + lane);
    float4 r1 = __ldg(r4 + lane + 32);
    float4 r2 = __ldg(r4 + lane + 64);
    float4 r3 = __ldg(r4 + lane + 96);

    const float4* base = (const float4*)(nodes + (size_t)k * NN * DD);
    const unsigned short* idx = g_idx + (size_t)k * NN;
    int slot0 = blockIdx.x * 64 + warp * 8;

    const float inv_sqrt_d = 0.04419417382415922f;  // 1/sqrt(512)
    float wsum = 0.f;

    if (slot0 < cnt) {
        #pragma unroll
        for (int i = 0; i < 8; i += 2) {
            int s0 = slot0 + i, s1 = s0 + 1;
            bool v0 = s0 < cnt, v1 = s1 < cnt;
            int n0 = v0 ? (int)idx[s0] : 0;   // clamp: harmless dummy load
            int n1 = v1 ? (int)idx[s1] : 0;

            const float4* p0 = base + (size_t)n0 * (DD / 4);
            const float4* p1 = base + (size_t)n1 * (DD / 4);

            float4 a0 = __ldcs(p0 + lane);
            float4 b0 = __ldcs(p0 + lane + 32);
            float4 c0 = __ldcs(p0 + lane + 64);
            float4 d0 = __ldcs(p0 + lane + 96);
            float4 a1 = __ldcs(p1 + lane);
            float4 b1 = __ldcs(p1 + lane + 32);
            float4 c1 = __ldcs(p1 + lane + 64);
            float4 d1 = __ldcs(p1 + lane + 96);

            float s0v = a0.x * r0.x + a0.y * r0.y + a0.z * r0.z + a0.w * r0.w
                      + b0.x * r1.x + b0.y * r1.y + b0.z * r1.z + b0.w * r1.w
                      + c0.x * r2.x + c0.y * r2.y + c0.z * r2.z + c0.w * r2.w
                      + d0.x * r3.x + d0.y * r3.y + d0.z * r3.z + d0.w * r3.w;
            float s1v = a1.x * r0.x + a1.y * r0.y + a1.z * r0.z + a1.w * r0.w
                      + b1.x * r1.x + b1.y * r1.y + b1.z * r1.z + b1.w * r1.w
                      + c1.x * r2.x + c1.y * r2.y + c1.z * r2.z + c1.w * r2.w
                      + d1.x * r3.x + d1.y * r3.y + d1.z * r3.z + d1.w * r3.w;

            #pragma unroll
            for (int o = 16; o > 0; o >>= 1) {
                s0v += __shfl_xor_sync(0xFFFFFFFFu, s0v, o);
                s1v += __shfl_xor_sync(0xFFFFFFFFu, s1v, o);
            }
            if (lane == 0) {
                if (v0) {
                    float e0 = __expf(tanhf(fminf(fmaxf(s0v, -10.f), 10.f)) * inv_sqrt_d);
                    g_exp[(size_t)k * NN + n0] = e0;
                    wsum += e0;
                }
                if (v1) {
                    float e1 = __expf(tanhf(fminf(fmaxf(s1v, -10.f), 10.f)) * inv_sqrt_d);
                    g_exp[(size_t)k * NN + n1] = e1;
                    wsum += e1;
                }
            }
        }
    }

    // CTA-level reduce of warp partials, single atomicAdd per CTA
    __shared__ float ws[8];
    if (lane == 0) ws[warp] = wsum;
    __syncthreads();
    if (tid == 0) {
        float s = 0.f;
        #pragma unroll
        for (int w = 0; w < 8; w++) s += ws[w];
        if (s != 0.f) atomicAdd(&g_rowsum[k], s);
    }
}

// ---------------------------------------------------------------------------
// Normalize: out = masked ? 0 : e / rowsum.  One CTA per row, 512 thr x 4 elems.
// ---------------------------------------------------------------------------
__global__ void normalize_kernel(const unsigned char* __restrict__ mask,
                                 float* __restrict__ out) {
    int k   = blockIdx.x;
    int tid = threadIdx.x;
    int mode = sniff_mask(mask);

    float inv = 1.f / g_rowsum[k];
    int n0 = tid * 4;
    size_t gi = (size_t)k * NN + n0;

    float4 e = *(const float4*)&g_exp[gi];
    float r[4] = {e.x, e.y, e.z, e.w};
    float o[4];
    #pragma unroll
    for (int j = 0; j < 4; j++) {
        bool m = mask_at(mask, mode, gi + j);
        o[j] = m ? 0.f : r[j] * inv;
    }
    *(float4*)&out[gi] = make_float4(o[0], o[1], o[2], o[3]);
}

// ---------------------------------------------------------------------------
extern "C" void kernel_launch(void* const* d_in, const int* in_sizes, int n_in,
                              void* d_out, int out_size) {
    const float* ctx   = (const float*)d_in[0];  // [128, 512]
    const float* nodes = (const float*)d_in[1];  // [128, 2048, 512]
    const unsigned char* mask = (const unsigned char*)d_in[2];  // [128, 2048]
    const float* Wq    = (const float*)d_in[3];  // [512, 512]
    const float* Wk    = (const float*)d_in[4];  // [512, 512]
    // d_in[5] = Wv: dead code in the reference output, skipped.
    float* out = (float*)d_out;                  // [128, 2048]

    gemm_kernel<0><<<dim3(DD / BN, KB / BM), 256>>>(ctx, Wq);      // q = c @ Wq^T
    gemm_kernel<1><<<dim3(DD / BN, KB / BM), 256>>>(nullptr, Wk);  // r = q @ Wk
    compact_kernel<<<KB, 256>>>(mask);                             // unmasked index lists
    dot_kernel<<<dim3(NN / 64, KB), 256>>>(nodes);                 // exp(compat), row sums
    normalize_kernel<<<KB, 512>>>(mask, out);                      // final weights
}